// round 11
// baseline (speedup 1.0000x reference)
#include <cuda_runtime.h>

typedef unsigned long long u64;

#define MAXN 100000
#define MAXE 1600000
#define D    128
#define SCAN_BS 512
#define MAX_SCAN_BLOCKS 256

// conv GEMM: 256 rows x 128 cols, 512 threads
#define GTC 256
#define ATS_C 260
#define AT_C_BYTES (128 * ATS_C * 4)       // 133120
#define WSTRIDE 140
#define W_BYTES (128 * WSTRIDE * 4)        // 71680
#define SMEM_C (AT_C_BYTES + W_BYTES)      // 204800

// heads GEMM: 128 rows x 2x128 cols, 512 threads
#define GTH 128
#define ATS_H 132
#define AT_H_BYTES (128 * ATS_H * 4)       // 67584
#define SMEM_H (AT_H_BYTES + 2 * W_BYTES)  // 210944

// ---------------- scratch (device globals; fully rewritten each launch) ----
__device__ __align__(16) float g_dis[MAXN];
__device__ __align__(16) float g_xw [(size_t)MAXN * D];
__device__ __align__(16) float g_h  [(size_t)MAXN * D];
__device__ int   g_cnt[MAXN];
__device__ int   g_incl[MAXN];
__device__ int   g_bsum[MAX_SCAN_BLOCKS];
__device__ int   g_rowstart[MAXN + 1];
__device__ int   g_cursor[MAXN];
__device__ __align__(16) int2 g_csr[MAXE];   // (src, coef-bits)
__device__ int g_is64;

// ---------------- edge dtype detection -------------------------------------
__global__ void k_detect(const int* __restrict__ e32, int nwords) {
    __shared__ int any;
    if (threadIdx.x == 0) any = 0;
    __syncthreads();
    int lim = nwords < 4096 ? nwords : 4096;
    for (int w = 1 + 2 * threadIdx.x; w < lim; w += 2 * blockDim.x)
        if (e32[w] != 0) any = 1;
    __syncthreads();
    if (threadIdx.x == 0) g_is64 = any ? 0 : 1;
}
__device__ __forceinline__ int edge_src(const int* e, int E, int i) {
    return g_is64 ? e[2 * (size_t)i] : e[i];
}
__device__ __forceinline__ int edge_dst(const int* e, int E, int i) {
    return g_is64 ? e[2 * ((size_t)E + i)] : e[(size_t)E + i];
}

// ---------------- zero (split so GEMM1 is the 4th launch for ncu) ----------
__global__ void k_zero_cnt(int n) {
    int i = blockIdx.x * blockDim.x + threadIdx.x;
    if (i < n) g_cnt[i] = 0;
}
__global__ void k_zero_cur(int n) {
    int i = blockIdx.x * blockDim.x + threadIdx.x;
    if (i < n) g_cursor[i] = 0;
}

// ---------------- CSR build -------------------------------------------------
__global__ void k_scan_block(int n) {
    __shared__ int sh[SCAN_BS];
    int i = blockIdx.x * SCAN_BS + threadIdx.x;
    int v = (i < n) ? g_cnt[i] : 0;
    if (i < n) g_dis[i] = rsqrtf((float)v + 1.0f);
    sh[threadIdx.x] = v;
    __syncthreads();
    #pragma unroll
    for (int off = 1; off < SCAN_BS; off <<= 1) {
        int t = (threadIdx.x >= off) ? sh[threadIdx.x - off] : 0;
        __syncthreads();
        sh[threadIdx.x] += t;
        __syncthreads();
    }
    if (i < n) g_incl[i] = sh[threadIdx.x];
    if (threadIdx.x == SCAN_BS - 1) g_bsum[blockIdx.x] = sh[threadIdx.x];
}
__global__ void k_scan_tops(int nblocks) {
    __shared__ int sh[MAX_SCAN_BLOCKS];
    int v = (threadIdx.x < nblocks) ? g_bsum[threadIdx.x] : 0;
    sh[threadIdx.x] = v;
    __syncthreads();
    #pragma unroll
    for (int off = 1; off < MAX_SCAN_BLOCKS; off <<= 1) {
        int t = (threadIdx.x >= off) ? sh[threadIdx.x - off] : 0;
        __syncthreads();
        sh[threadIdx.x] += t;
        __syncthreads();
    }
    g_bsum[threadIdx.x] = sh[threadIdx.x] - v;
}
__global__ void k_scan_add(int n, int E) {
    int i = blockIdx.x * SCAN_BS + threadIdx.x;
    if (i < n) {
        int excl = g_incl[i] - g_cnt[i] + g_bsum[blockIdx.x];
        g_rowstart[i] = excl;
        if (i == n - 1) g_rowstart[n] = excl + g_cnt[i];
    }
}
__global__ void k_fill(const int* __restrict__ edge, int E) {
    int i = blockIdx.x * blockDim.x + threadIdx.x;
    if (i < E) {
        int s = edge_src(edge, E, i);
        int d = edge_dst(edge, E, i);
        int pos = g_rowstart[d] + atomicAdd(&g_cursor[d], 1);
        g_csr[pos] = make_int2(s, __float_as_int(g_dis[s] * g_dis[d]));
    }
}

// ---------------- f32x2 helpers ---------------------------------------------
union F2U  { float2 f; u64 u; };
union F4U2 { float4 f; ulonglong2 u; };
__device__ __forceinline__ u64 dup_f32x2(float x) {
    F2U t; t.f = make_float2(x, x); return t.u;
}
__device__ __forceinline__ void ffma2(u64& acc, u64 a, u64 w) {
    asm("fma.rn.f32x2 %0, %1, %2, %0;" : "+l"(acc) : "l"(a), "l"(w));
}
__device__ __forceinline__ int wskew(int c) { return c + 4 * (c >> 5); }

// ---------------- GEMM core: warp = 16 rows (broadcast A), lane = 4 cols ----
// acc[rp][c] = f32x2 over row-pair (rbase+2rp, rbase+2rp+1), col cbase+c.
// Per k: 4 broadcast LDS.128 (A, natural row-pairs) + 1 LDS.128 (W)
//        + 4 dup MOVs + 32 FFMA2.
__device__ __forceinline__ void gemm_core(const float* __restrict__ At, int ats,
                                          const float* __restrict__ Ws,
                                          int rbase, int cb, u64 acc[8][4])
{
    #pragma unroll 4
    for (int k = 0; k < 128; k++) {
        int sw = ((k >> 2) & 7) << 2;
        const float* atk = At + k * ats;
        F4U2 a0, a1, a2, a3;
        a0.f = *(const float4*)(atk + ((rbase     ) ^ sw));
        a1.f = *(const float4*)(atk + ((rbase +  4) ^ sw));
        a2.f = *(const float4*)(atk + ((rbase +  8) ^ sw));
        a3.f = *(const float4*)(atk + ((rbase + 12) ^ sw));
        float4 wv = *(const float4*)(Ws + k * WSTRIDE + cb);
        u64 w0 = dup_f32x2(wv.x), w1 = dup_f32x2(wv.y);
        u64 w2 = dup_f32x2(wv.z), w3 = dup_f32x2(wv.w);
        ffma2(acc[0][0], a0.u.x, w0); ffma2(acc[0][1], a0.u.x, w1);
        ffma2(acc[0][2], a0.u.x, w2); ffma2(acc[0][3], a0.u.x, w3);
        ffma2(acc[1][0], a0.u.y, w0); ffma2(acc[1][1], a0.u.y, w1);
        ffma2(acc[1][2], a0.u.y, w2); ffma2(acc[1][3], a0.u.y, w3);
        ffma2(acc[2][0], a1.u.x, w0); ffma2(acc[2][1], a1.u.x, w1);
        ffma2(acc[2][2], a1.u.x, w2); ffma2(acc[2][3], a1.u.x, w3);
        ffma2(acc[3][0], a1.u.y, w0); ffma2(acc[3][1], a1.u.y, w1);
        ffma2(acc[3][2], a1.u.y, w2); ffma2(acc[3][3], a1.u.y, w3);
        ffma2(acc[4][0], a2.u.x, w0); ffma2(acc[4][1], a2.u.x, w1);
        ffma2(acc[4][2], a2.u.x, w2); ffma2(acc[4][3], a2.u.x, w3);
        ffma2(acc[5][0], a2.u.y, w0); ffma2(acc[5][1], a2.u.y, w1);
        ffma2(acc[5][2], a2.u.y, w2); ffma2(acc[5][3], a2.u.y, w3);
        ffma2(acc[6][0], a3.u.x, w0); ffma2(acc[6][1], a3.u.x, w1);
        ffma2(acc[6][2], a3.u.x, w2); ffma2(acc[6][3], a3.u.x, w3);
        ffma2(acc[7][0], a3.u.y, w0); ffma2(acc[7][1], a3.u.y, w1);
        ffma2(acc[7][2], a3.u.y, w2); ffma2(acc[7][3], a3.u.y, w3);
    }
}

// ---------------- conv GEMM: out = A @ W (no bias/relu) ---------------------
__global__ void __launch_bounds__(512, 1)
k_gemm_c(const float* __restrict__ A, int n,
         const float* __restrict__ W, float* __restrict__ out,
         const int* __restrict__ edge, int E, int hist)
{
    extern __shared__ __align__(16) char smem[];
    float* At = (float*)smem;                      // [128][ATS_C] swizzled
    float* Ws = (float*)(smem + AT_C_BYTES);       // [128][WSTRIDE] skewed

    const int tid = threadIdx.x;
    const int rowBlock = blockIdx.x * GTC;

    if (hist) {
        int per  = (E + gridDim.x - 1) / gridDim.x;
        int base = blockIdx.x * per;
        int lim  = base + per; if (lim > E) lim = E;
        for (int i = base + tid; i < lim; i += 512)
            atomicAdd(&g_cnt[edge_dst(edge, E, i)], 1);
    }

    // fill At: At[k][r ^ swz(k)] = A[r][k]
    #pragma unroll
    for (int i = 0; i < 16; i++) {
        int idx = tid + i * 512;           // 8192: r (0..255), c4 (0..31)
        int r   = idx >> 5;
        int c4  = idx & 31;
        int grow = rowBlock + r;
        float4 v = make_float4(0.f, 0.f, 0.f, 0.f);
        if (grow < n) v = ((const float4*)(A + (size_t)grow * D))[c4];
        int rs = r ^ ((c4 & 7) << 2);
        int k0 = 4 * c4;
        At[(k0 + 0) * ATS_C + rs] = v.x;
        At[(k0 + 1) * ATS_C + rs] = v.y;
        At[(k0 + 2) * ATS_C + rs] = v.z;
        At[(k0 + 3) * ATS_C + rs] = v.w;
    }
    // fill Ws skewed
    #pragma unroll
    for (int i = 0; i < 8; i++) {
        int idx = tid + i * 512;
        int k   = idx >> 5;
        int c4  = idx & 31;
        float4 v = ((const float4*)(W + (size_t)k * D))[c4];
        *(float4*)(Ws + k * WSTRIDE + wskew(4 * c4)) = v;
    }
    __syncthreads();

    const int wid  = tid >> 5, lane = tid & 31;
    const int rbase = wid * 16;
    const int cbase = lane * 4;
    const int cb    = wskew(cbase);

    u64 acc[8][4];
    #pragma unroll
    for (int rp = 0; rp < 8; rp++)
        #pragma unroll
        for (int c = 0; c < 4; c++) acc[rp][c] = 0ull;

    gemm_core(At, ATS_C, Ws, rbase, cb, acc);

    #pragma unroll
    for (int rp = 0; rp < 8; rp++) {
        int r0 = rowBlock + rbase + 2 * rp;
        F2U p0, p1, p2, p3;
        p0.u = acc[rp][0]; p1.u = acc[rp][1];
        p2.u = acc[rp][2]; p3.u = acc[rp][3];
        if (r0 < n)
            *(float4*)(out + (size_t)r0 * D + cbase) =
                make_float4(p0.f.x, p1.f.x, p2.f.x, p3.f.x);
        if (r0 + 1 < n)
            *(float4*)(out + (size_t)(r0 + 1) * D + cbase) =
                make_float4(p0.f.y, p1.f.y, p2.f.y, p3.f.y);
    }
}

// ---------------- heads GEMM: outv/outt = relu(A@Wv+bv / A@Wt+bt) -----------
// 128 rows; warps 0-7 -> head V, warps 8-15 -> head T (16 rows each).
__global__ void __launch_bounds__(512, 1)
k_gemm_h(const float* __restrict__ A, int n,
         const float* __restrict__ Wv, const float* __restrict__ bv,
         float* __restrict__ outv,
         const float* __restrict__ Wt, const float* __restrict__ bt,
         float* __restrict__ outt)
{
    extern __shared__ __align__(16) char smem[];
    float* At = (float*)smem;                        // [128][ATS_H]
    float* Ws = (float*)(smem + AT_H_BYTES);         // [2][128][WSTRIDE]

    const int tid = threadIdx.x;
    const int rowBlock = blockIdx.x * GTH;

    #pragma unroll
    for (int i = 0; i < 8; i++) {
        int idx = tid + i * 512;           // 4096: r (0..127), c4
        int r   = idx >> 5;
        int c4  = idx & 31;
        int grow = rowBlock + r;
        float4 v = make_float4(0.f, 0.f, 0.f, 0.f);
        if (grow < n) v = ((const float4*)(A + (size_t)grow * D))[c4];
        int rs = r ^ ((c4 & 7) << 2);
        int k0 = 4 * c4;
        At[(k0 + 0) * ATS_H + rs] = v.x;
        At[(k0 + 1) * ATS_H + rs] = v.y;
        At[(k0 + 2) * ATS_H + rs] = v.z;
        At[(k0 + 3) * ATS_H + rs] = v.w;
    }
    #pragma unroll
    for (int i = 0; i < 16; i++) {
        int idx = tid + i * 512;           // 8192: half, k, c4
        int half = idx >> 12;
        int j    = idx & 4095;
        int k    = j >> 5;
        int c4   = j & 31;
        const float* W = half ? Wt : Wv;
        float4 v = ((const float4*)(W + (size_t)k * D))[c4];
        *(float4*)(Ws + half * (W_BYTES / 4) + k * WSTRIDE + wskew(4 * c4)) = v;
    }
    __syncthreads();

    const int wid  = tid >> 5, lane = tid & 31;
    const int head = wid >> 3;
    const int rbase = (wid & 7) * 16;
    const int cbase = lane * 4;
    const int cb    = wskew(cbase);
    const float* Wsh = Ws + head * (W_BYTES / 4);

    u64 acc[8][4];
    #pragma unroll
    for (int rp = 0; rp < 8; rp++)
        #pragma unroll
        for (int c = 0; c < 4; c++) acc[rp][c] = 0ull;

    gemm_core(At, ATS_H, Wsh, rbase, cb, acc);

    const float* bias = head ? bt : bv;
    float*       out  = head ? outt : outv;
    float4 b = *(const float4*)(bias + cbase);
    #pragma unroll
    for (int rp = 0; rp < 8; rp++) {
        int r0 = rowBlock + rbase + 2 * rp;
        F2U p0, p1, p2, p3;
        p0.u = acc[rp][0]; p1.u = acc[rp][1];
        p2.u = acc[rp][2]; p3.u = acc[rp][3];
        if (r0 < n) {
            float4 o = make_float4(fmaxf(p0.f.x + b.x, 0.f),
                                   fmaxf(p1.f.x + b.y, 0.f),
                                   fmaxf(p2.f.x + b.z, 0.f),
                                   fmaxf(p3.f.x + b.w, 0.f));
            *(float4*)(out + (size_t)r0 * D + cbase) = o;
        }
        if (r0 + 1 < n) {
            float4 o = make_float4(fmaxf(p0.f.y + b.x, 0.f),
                                   fmaxf(p1.f.y + b.y, 0.f),
                                   fmaxf(p2.f.y + b.z, 0.f),
                                   fmaxf(p3.f.y + b.w, 0.f));
            *(float4*)(out + (size_t)(r0 + 1) * D + cbase) = o;
        }
    }
}

// ---------------- CSR gather aggregation -----------------------------------
__global__ void k_gather(const float* __restrict__ xw,
                         float* __restrict__ out,
                         const float* __restrict__ bias, int relu,
                         int n)
{
    int warp = (blockIdx.x * blockDim.x + threadIdx.x) >> 5;
    int lane = threadIdx.x & 31;
    if (warp >= n) return;
    const int d = warp;

    float dis = g_dis[d];
    float dis2 = dis * dis;
    float4 self = ((const float4*)(xw + (size_t)d * D))[lane];
    float4 acc;
    acc.x = self.x * dis2; acc.y = self.y * dis2;
    acc.z = self.z * dis2; acc.w = self.w * dis2;

    int e   = g_rowstart[d];
    int end = g_rowstart[d + 1];

    for (; e + 1 < end; e += 2) {
        int2 e0 = g_csr[e];
        int2 e1 = g_csr[e + 1];
        float c0 = __int_as_float(e0.y);
        float c1 = __int_as_float(e1.y);
        float4 v0 = ((const float4*)(xw + (size_t)e0.x * D))[lane];
        float4 v1 = ((const float4*)(xw + (size_t)e1.x * D))[lane];
        acc.x = fmaf(c0, v0.x, acc.x); acc.y = fmaf(c0, v0.y, acc.y);
        acc.z = fmaf(c0, v0.z, acc.z); acc.w = fmaf(c0, v0.w, acc.w);
        acc.x = fmaf(c1, v1.x, acc.x); acc.y = fmaf(c1, v1.y, acc.y);
        acc.z = fmaf(c1, v1.z, acc.z); acc.w = fmaf(c1, v1.w, acc.w);
    }
    if (e < end) {
        int2 e0 = g_csr[e];
        float c0 = __int_as_float(e0.y);
        float4 v0 = ((const float4*)(xw + (size_t)e0.x * D))[lane];
        acc.x = fmaf(c0, v0.x, acc.x); acc.y = fmaf(c0, v0.y, acc.y);
        acc.z = fmaf(c0, v0.z, acc.z); acc.w = fmaf(c0, v0.w, acc.w);
    }

    const int col = lane * 4;
    acc.x += bias[col]; acc.y += bias[col + 1];
    acc.z += bias[col + 2]; acc.w += bias[col + 3];
    if (relu) {
        acc.x = fmaxf(acc.x, 0.f); acc.y = fmaxf(acc.y, 0.f);
        acc.z = fmaxf(acc.z, 0.f); acc.w = fmaxf(acc.w, 0.f);
    }
    ((float4*)(out + (size_t)d * D))[lane] = acc;
}

// ---------------- launch ---------------------------------------------------
extern "C" void kernel_launch(void* const* d_in, const int* in_sizes, int n_in,
                              void* d_out, int out_size)
{
    const float* x    = (const float*)d_in[0];
    const int*   edge = (const int*)d_in[1];   // int32 or int64 (detected)
    const float* W1 = (const float*)d_in[2]; const float* b1 = (const float*)d_in[3];
    const float* W2 = (const float*)d_in[4]; const float* b2 = (const float*)d_in[5];
    const float* Wv = (const float*)d_in[6]; const float* bv = (const float*)d_in[7];
    const float* Wt = (const float*)d_in[8]; const float* bt = (const float*)d_in[9];

    const int n = in_sizes[0] / D;
    const int E = in_sizes[1] / 2;

    float* out_h = (float*)d_out;
    float* out_v = out_h + (size_t)n * D;
    float* out_t = out_v + (size_t)n * D;

    float* xw = nullptr; cudaGetSymbolAddress((void**)&xw, g_xw);
    float* h  = nullptr; cudaGetSymbolAddress((void**)&h,  g_h);

    cudaFuncSetAttribute(k_gemm_c, cudaFuncAttributeMaxDynamicSharedMemorySize, SMEM_C);
    cudaFuncSetAttribute(k_gemm_h, cudaFuncAttributeMaxDynamicSharedMemorySize, SMEM_H);

    const int TB = 256;
    const int nscan = (n + SCAN_BS - 1) / SCAN_BS;
    const int convGrid   = (n + GTC - 1) / GTC;
    const int headGrid   = (n + GTH - 1) / GTH;
    const int gatherGrid = (n + 7) / 8;

    // launches 1-3 small so the conv1 GEMM is the 4th (ncu sample slot)
    k_detect<<<1, 512>>>(edge, 2 * E);
    k_zero_cnt<<<(n + TB - 1) / TB, TB>>>(n);
    k_zero_cur<<<(n + TB - 1) / TB, TB>>>(n);
    // 4: conv1 GEMM (+ folded degree histogram)
    k_gemm_c<<<convGrid, 512, SMEM_C>>>(x, n, W1, xw, edge, E, 1);
    // normalization + CSR
    k_scan_block<<<nscan, SCAN_BS>>>(n);
    k_scan_tops<<<1, MAX_SCAN_BLOCKS>>>(nscan);
    k_scan_add<<<nscan, SCAN_BS>>>(n, E);
    k_fill<<<(E + TB - 1) / TB, TB>>>(edge, E);
    // conv1 aggregate -> h
    k_gather<<<gatherGrid, TB>>>(xw, h, b1, 1, n);
    // conv2
    k_gemm_c<<<convGrid, 512, SMEM_C>>>(h, n, W2, xw, nullptr, 0, 0);
    k_gather<<<gatherGrid, TB>>>(xw, out_h, b2, 0, n);
    // heads: one launch, both W
    k_gemm_h<<<headGrid, 512, SMEM_H>>>(out_h, n, Wv, bv, out_v, Wt, bt, out_t);
}